// round 16
// baseline (speedup 1.0000x reference)
#include <cuda_runtime.h>
#include <cuda_bf16.h>
#include <cuda_fp16.h>
#include <cstdint>

// ---------------------------------------------------------------------------
// BiLevelRoutingAttention, B=1, H=W=112, DIM=QK=256, HEADS=8, NWIN=7, TOPK=4
// gemm0: single-term fp16, A gathered from x in-kernel; KV pack staged
// through smem (block-local head slots) for coalesced stores.
// gemm1: single-term fp16. Attention v8: per-key-group pipeline.
// ---------------------------------------------------------------------------

#define P2     49
#define W2     256
#define MROWS  12544
#define NQKV   768
#define KDIM   256
#define IMG    112
#define QSCALE 0.09016844f   // 256^-0.5 * log2(e)

__device__ float g_qkv [MROWS * 512];              // q (stride 512)
__device__ float g_vimg[MROWS * 256];              // v, image layout
__device__ float g_part2[98][512];                 // per half-window column sums
__device__ int   g_top [P2 * 4];
__device__ float g_y   [MROWS * 256];              // attn out, image layout
__device__ __half g_Yp[MROWS * 512];               // attn+lepe   [hi| - ]
__device__ __half g_Bq[NQKV * 512];                // w_qkv^T     [hi| - ]
__device__ __half g_Bo[KDIM * 512];                // w_o^T       [hi| - ]
// Packed K/V tiles (fp16): per (win,h): 256 rows x 128B; only hi half used.
__device__ unsigned char g_Ktb[P2 * 8 * 32768];
__device__ unsigned char g_Vtb[P2 * 8 * 32768];

__device__ __forceinline__ uint32_t smem_u32(const void* p) {
    uint32_t a;
    asm("{ .reg .u64 t; cvta.to.shared.u64 t, %1; cvt.u32.u64 %0, t; }" : "=r"(a) : "l"(p));
    return a;
}
__device__ __forceinline__ uint32_t pack_h2(__half lo, __half hi) {
    return ((uint32_t)__half_as_ushort(hi) << 16) | __half_as_ushort(lo);
}
__device__ __forceinline__ uint32_t cvt_h2(float lo, float hi) {
    uint32_t d;
    asm("cvt.rn.f16x2.f32 %0, %1, %2;" : "=r"(d) : "f"(hi), "f"(lo));
    return d;
}
__device__ __forceinline__ uint32_t exp2_h2(float hi, float lo) {
    uint32_t d;
    asm("cvt.rn.f16x2.f32 %0, %1, %2;" : "=r"(d) : "f"(hi), "f"(lo));
    asm("sub.f16x2 %0, %0, %1;" : "+r"(d) : "r"(0x46004600u));   // 6.0 | 6.0
    asm("ex2.approx.f16x2 %0, %0;" : "+r"(d));
    return d;
}
__device__ __forceinline__ void ldsm_x4(uint32_t& r0, uint32_t& r1, uint32_t& r2, uint32_t& r3, uint32_t a) {
    asm volatile("ldmatrix.sync.aligned.m8n8.x4.shared.b16 {%0,%1,%2,%3}, [%4];"
                 : "=r"(r0), "=r"(r1), "=r"(r2), "=r"(r3) : "r"(a));
}
__device__ __forceinline__ void ldsm_x4_t(uint32_t& r0, uint32_t& r1, uint32_t& r2, uint32_t& r3, uint32_t a) {
    asm volatile("ldmatrix.sync.aligned.m8n8.x4.trans.shared.b16 {%0,%1,%2,%3}, [%4];"
                 : "=r"(r0), "=r"(r1), "=r"(r2), "=r"(r3) : "r"(a));
}
__device__ __forceinline__ void mma16816h(float* c, const uint32_t* a, const uint32_t* b) {
    asm volatile(
        "mma.sync.aligned.m16n8k16.row.col.f32.f16.f16.f32 "
        "{%0,%1,%2,%3}, {%4,%5,%6,%7}, {%8,%9}, {%0,%1,%2,%3};"
        : "+f"(c[0]), "+f"(c[1]), "+f"(c[2]), "+f"(c[3])
        : "r"(a[0]), "r"(a[1]), "r"(a[2]), "r"(a[3]), "r"(b[0]), "r"(b[1]));
}
#define CP_ASYNC16(sa, gp) asm volatile("cp.async.cg.shared.global [%0], [%1], 16;" :: "r"(sa), "l"(gp) : "memory")
#define CP_COMMIT()        asm volatile("cp.async.commit_group;" ::: "memory")
#define CP_WAIT0()         asm volatile("cp.async.wait_group 0;" ::: "memory")

// ---------------------------------------------------------------------------
// Prep: weight transpose to fp16
// ---------------------------------------------------------------------------
__global__ __launch_bounds__(256) void prep_w(const float* __restrict__ wq,
                                              const float* __restrict__ wo) {
    const int t = blockIdx.x * 256 + threadIdx.x;
    const int n = t >> 8, k = t & 255;
    g_Bq[n * 512 + k] = __float2half_rn(wq[k * NQKV + n]);
    if (t < KDIM * KDIM)
        g_Bo[n * 512 + k] = __float2half_rn(wo[k * KDIM + n]);
}
__global__ void nop_k() {}

// ---------------------------------------------------------------------------
// Dense GEMM fp16 single-term, 4 k-tiles.
// MODE 0: A gathered from x; KV pack staged through smem (block-local heads);
//         v image scatter; window column sums. MODE 1: A = g_Yp; plain output.
// ---------------------------------------------------------------------------
template <int MODE>
__global__ __launch_bounds__(256) void gemm_mma(const float* __restrict__ X,
                                                const float* __restrict__ bias,
                                                float* __restrict__ Cout) {
    __shared__ __align__(128) unsigned char SM[32768 + 2048];
    __half* As = (__half*)SM;
    __half* Bs = (__half*)(SM + 16384);
    float (*sWsum)[64] = (float(*)[64])(SM + 32768);

    const __half* B = (MODE == 0) ? g_Bq : g_Bo;

    const int tid  = threadIdx.x;
    const int wid  = tid >> 5;
    const int lane = tid & 31;
    const int m0   = blockIdx.y * 128;
    const int n0   = blockIdx.x * 128;
    const int mw   = (wid >> 1) * 32;
    const int nw   = (wid & 1) * 64;

    const uint32_t sA = smem_u32(As), sB = smem_u32(Bs);

    int grow[4], gchk[4], soff[4];
    const float* Arow[4];
#pragma unroll
    for (int i = 0; i < 4; i++) {
        const int idx = tid + 256 * i;
        grow[i] = idx >> 3;
        gchk[i] = idx & 7;
        soff[i] = grow[i] * 128 + ((gchk[i] ^ (grow[i] & 7)) * 16);
        const int m = m0 + grow[i];
        if (MODE == 0) {
            const int p = m >> 8, pix = m & 255;
            const int gy = (p / 7) * 16 + (pix >> 4);
            const int gx = (p % 7) * 16 + (pix & 15);
            Arow[i] = X + (size_t)(gy * IMG + gx) * KDIM + gchk[i] * 8;
        } else {
            Arow[i] = (const float*)(g_Yp + (size_t)m * 512 + gchk[i] * 8);
        }
    }

    uint4 pb[4];
#pragma unroll
    for (int i = 0; i < 4; i++)
        pb[i] = *(const uint4*)(B + (size_t)(n0 + grow[i]) * 512 + gchk[i] * 8);

    float acc[2][8][4];
#pragma unroll
    for (int mt = 0; mt < 2; mt++)
#pragma unroll
        for (int nt = 0; nt < 8; nt++)
#pragma unroll
            for (int j = 0; j < 4; j++) acc[mt][nt][j] = 0.f;

    for (int kt = 0; kt < 4; kt++) {
#pragma unroll
        for (int i = 0; i < 4; i++) {
            uint4 hv;
            if (MODE == 0) {
                const float4 f0 = *(const float4*)(Arow[i] + kt * 64);
                const float4 f1 = *(const float4*)(Arow[i] + kt * 64 + 4);
                hv.x = cvt_h2(f0.x, f0.y);
                hv.y = cvt_h2(f0.z, f0.w);
                hv.z = cvt_h2(f1.x, f1.y);
                hv.w = cvt_h2(f1.z, f1.w);
            } else {
                hv = *(const uint4*)((const __half*)Arow[i] + kt * 64);
            }
            *(uint4*)(SM + soff[i]) = hv;
            *(uint4*)(SM + 16384 + soff[i]) = pb[i];
        }
        __syncthreads();
        if (kt + 1 < 4) {
            const int bo = (kt + 1) * 64;
#pragma unroll
            for (int i = 0; i < 4; i++)
                pb[i] = *(const uint4*)(B + (size_t)(n0 + grow[i]) * 512 + bo + gchk[i] * 8);
        }
#pragma unroll
        for (int ks = 0; ks < 4; ks++) {
            uint32_t aF[2][4];
#pragma unroll
            for (int mt = 0; mt < 2; mt++) {
                const int row = mw + mt * 16 + (lane & 15);
                const int chk = ks * 2 + (lane >> 4);
                ldsm_x4(aF[mt][0], aF[mt][1], aF[mt][2], aF[mt][3],
                        sA + row * 128 + ((chk ^ (row & 7)) * 16));
            }
            uint32_t bF[8][2];
#pragma unroll
            for (int np = 0; np < 4; np++) {
                const int row = nw + np * 16 + (lane & 7) + ((lane >> 4) << 3);
                const int chk = ks * 2 + ((lane >> 3) & 1);
                uint32_t r0, r1, r2, r3;
                ldsm_x4(r0, r1, r2, r3, sB + row * 128 + ((chk ^ (row & 7)) * 16));
                bF[np * 2][0] = r0; bF[np * 2][1] = r1;
                bF[np * 2 + 1][0] = r2; bF[np * 2 + 1][1] = r3;
            }
#pragma unroll
            for (int mt = 0; mt < 2; mt++)
#pragma unroll
                for (int nt = 0; nt < 8; nt++)
                    mma16816h(acc[mt][nt], aF[mt], bF[nt]);
        }
        __syncthreads();
    }

    const int r0 = lane >> 2, c0 = (lane & 3) * 2;
    const int kind = (MODE == 0) ? ((n0 >= 512) ? 2 : ((n0 >= 256) ? 1 : 0)) : 0;

    float cs[8][2];
#pragma unroll
    for (int nt = 0; nt < 8; nt++) { cs[nt][0] = 0.f; cs[nt][1] = 0.f; }

#pragma unroll
    for (int mt = 0; mt < 2; mt++) {
#pragma unroll
        for (int nt = 0; nt < 8; nt++) {
            const int col = n0 + nw + nt * 8 + c0;
            const float bx = bias[col], by = bias[col + 1];
            const int rowa = m0 + mw + mt * 16 + r0;
            const float vx[2] = {acc[mt][nt][0] + bx, acc[mt][nt][2] + bx};
            const float vy[2] = {acc[mt][nt][1] + by, acc[mt][nt][3] + by};
            if (MODE == 1) {
                *(float2*)(Cout + (size_t)rowa * KDIM + col)       = make_float2(vx[0], vy[0]);
                *(float2*)(Cout + (size_t)(rowa + 8) * KDIM + col) = make_float2(vx[1], vy[1]);
            } else {
                cs[nt][0] += vx[0] + vx[1];
                cs[nt][1] += vy[0] + vy[1];
#pragma unroll
                for (int rr = 0; rr < 2; rr++) {
                    const int row = rowa + rr * 8;
                    if (kind == 0)
                        *(float2*)(g_qkv + (size_t)row * 512 + col) = make_float2(vx[rr], vy[rr]);
                    if (kind >= 1) {
                        // stage: block-LOCAL head slot hl = (col - n0)>>5 in 0..3
                        const int hl = (col - n0) >> 5;
                        const int w  = ((col - n0) & 31) >> 1;
                        const int jl = mw + mt * 16 + r0 + rr * 8;
                        *(uint32_t*)(SM + hl * 8192 + jl * 64 + (w >> 2) * 16 + (w & 3) * 4)
                            = pack_h2(__float2half_rn(vx[rr]), __float2half_rn(vy[rr]));
                    }
                    if (kind == 2) {
                        const int p = row >> 8, pix = row & 255;
                        const int gy = (p / 7) * 16 + (pix >> 4);
                        const int gx = (p % 7) * 16 + (pix & 15);
                        *(float2*)(g_vimg + ((size_t)(gy * IMG + gx)) * 256 + (col - 512))
                            = make_float2(vx[rr], vy[rr]);
                    }
                }
            }
        }
    }

    if (MODE == 0 && kind >= 1) {
        __syncthreads();
        const int pwin  = m0 >> 8;
        const int jbase = m0 & 255;
        const int hbase = (n0 - ((kind == 1) ? 256 : 512)) >> 5;   // 0 or 4
        unsigned char* tb0 = ((kind == 1) ? g_Ktb : g_Vtb)
                           + ((size_t)pwin * 8 + hbase) * 32768;
#pragma unroll
        for (int i = 0; i < 8; i++) {
            const int idx = tid + i * 256;          // 0..2047
            const int hh = idx >> 9;                // local head 0..3
            const int j  = (idx >> 2) & 127;
            const int sl = idx & 3;
            const int jj = jbase + j;
            *(uint4*)(tb0 + (size_t)hh * 32768 + jj * 128 + ((sl ^ (jj & 7)) * 16))
                = *(const uint4*)(SM + hh * 8192 + j * 64 + sl * 16);
        }
    }

    if (MODE == 0 && kind < 2) {
#pragma unroll
        for (int nt = 0; nt < 8; nt++) {
            float a = cs[nt][0], b = cs[nt][1];
#pragma unroll
            for (int o = 4; o < 32; o <<= 1) {
                a += __shfl_xor_sync(0xffffffffu, a, o);
                b += __shfl_xor_sync(0xffffffffu, b, o);
            }
            if (lane < 4) {
                sWsum[wid][nt * 8 + c0]     = a;
                sWsum[wid][nt * 8 + c0 + 1] = b;
            }
        }
        __syncthreads();
        if (tid < 128) {
            const int nwsel = tid >> 6, col = tid & 63;
            const float s = sWsum[nwsel][col] + sWsum[2 + nwsel][col]
                          + sWsum[4 + nwsel][col] + sWsum[6 + nwsel][col];
            g_part2[m0 >> 7][n0 + nwsel * 64 + col] = s;
        }
    }
}

// ---------------------------------------------------------------------------
// Routing: block p: q-row sum, logits vs all k-row sums, top-4.
// ---------------------------------------------------------------------------
__global__ __launch_bounds__(256) void route_k() {
    __shared__ float sq[256];
    __shared__ float slog[64];
    const int p = blockIdx.x, tid = threadIdx.x, wrp = tid >> 5, lane = tid & 31;

    sq[tid] = g_part2[2 * p][tid] + g_part2[2 * p + 1][tid];
    __syncthreads();

    const float q0 = sq[lane * 8 + 0], q1 = sq[lane * 8 + 1];
    const float q2 = sq[lane * 8 + 2], q3 = sq[lane * 8 + 3];
    const float q4 = sq[lane * 8 + 4], q5 = sq[lane * 8 + 5];
    const float q6 = sq[lane * 8 + 6], q7 = sq[lane * 8 + 7];
    for (int j = wrp; j < P2; j += 8) {
        const float4 a0 = *(const float4*)&g_part2[2 * j][256 + lane * 8];
        const float4 a1 = *(const float4*)&g_part2[2 * j][256 + lane * 8 + 4];
        const float4 b0 = *(const float4*)&g_part2[2 * j + 1][256 + lane * 8];
        const float4 b1 = *(const float4*)&g_part2[2 * j + 1][256 + lane * 8 + 4];
        float d = q0 * (a0.x + b0.x) + q1 * (a0.y + b0.y)
                + q2 * (a0.z + b0.z) + q3 * (a0.w + b0.w)
                + q4 * (a1.x + b1.x) + q5 * (a1.y + b1.y)
                + q6 * (a1.z + b1.z) + q7 * (a1.w + b1.w);
#pragma unroll
        for (int o = 16; o > 0; o >>= 1) d += __shfl_xor_sync(0xffffffffu, d, o);
        if (lane == 0) slog[j] = d;
    }
    __syncthreads();

    if (tid == 0) {
        float bv0 = -1e30f, bv1 = -1e30f, bv2 = -1e30f, bv3 = -1e30f;
        int   bi0 = 0, bi1 = 0, bi2 = 0, bi3 = 0;
        for (int j = 0; j < P2; j++) {
            const float s = slog[j];
            if (s > bv3) {
                if (s > bv0)      { bv3=bv2;bi3=bi2; bv2=bv1;bi2=bi1; bv1=bv0;bi1=bi0; bv0=s;bi0=j; }
                else if (s > bv1) { bv3=bv2;bi3=bi2; bv2=bv1;bi2=bi1; bv1=s;bi1=j; }
                else if (s > bv2) { bv3=bv2;bi3=bi2; bv2=s;bi2=j; }
                else              { bv3=s;bi3=j; }
            }
        }
        g_top[p * 4 + 0] = bi0; g_top[p * 4 + 1] = bi1;
        g_top[p * 4 + 2] = bi2; g_top[p * 4 + 3] = bi3;
    }
}

// ---------------------------------------------------------------------------
// Attention v8: grid (49, 8, 2); 128 threads (4 warps x 32 q rows).
// Per-key-group pipeline: QK -> exp2 -> l -> PV per 16 keys. cp.async fills.
// ---------------------------------------------------------------------------
__global__ __launch_bounds__(128) void attn_mma() {
    __shared__ __align__(128) unsigned char Kt[16384];
    __shared__ __align__(128) unsigned char Vt[16384];
    __shared__ int sidx[4];
    const int p = blockIdx.x, h = blockIdx.y, qz = blockIdx.z;
    const int tid = threadIdx.x, wid = tid >> 5, lane = tid & 31;
    if (tid < 4) sidx[tid] = g_top[p * 4 + tid];

    const uint32_t sK = smem_u32(Kt), sV = smem_u32(Vt);
    const int r  = lane >> 2;
    const int c2 = (lane & 3) * 2;

    int loff[2];
#pragma unroll
    for (int i = 0; i < 2; i++) {
        const int t = tid + i * 128;
        const int lrow = t >> 2, lc = t & 3;
        loff[i] = lrow * 128 + ((lc ^ (lrow & 7)) * 16);
    }

    uint32_t qh[2][2][4];
    {
        const float* qb = g_qkv + ((size_t)p * W2 + qz * 128 + wid * 32) * 512 + h * 32;
#pragma unroll
        for (int mt = 0; mt < 2; mt++)
#pragma unroll
            for (int ks = 0; ks < 2; ks++)
#pragma unroll
                for (int idx = 0; idx < 4; idx++) {
                    const int row = mt * 16 + r + (idx & 1) * 8;
                    const int col = ks * 16 + (idx >> 1) * 8 + c2;
                    const float2 v = *(const float2*)(qb + (size_t)row * 512 + col);
                    qh[mt][ks][idx] = pack_h2(__float2half_rn(v.x * QSCALE),
                                              __float2half_rn(v.y * QSCALE));
                }
    }
    __syncthreads();
    const int s0 = sidx[0], s1 = sidx[1], s2_ = sidx[2], s3 = sidx[3];

    float lacc[2][4];
    float outA[2][4][4];
#pragma unroll
    for (int mt = 0; mt < 2; mt++) {
#pragma unroll
        for (int j = 0; j < 4; j++) lacc[mt][j] = 0.f;
#pragma unroll
        for (int ct = 0; ct < 4; ct++)
#pragma unroll
            for (int j = 0; j < 4; j++) outA[mt][ct][j] = 0.f;
    }
    const uint32_t ONE2 = 0x3C003C00u;
    const uint32_t bones[2] = {ONE2, ONE2};

    {
        const size_t b = ((size_t)(s0 * 8 + h)) * 32768;
#pragma unroll
        for (int i = 0; i < 2; i++) {
            CP_ASYNC16(sK + loff[i], g_Ktb + b + loff[i]);
            CP_ASYNC16(sV + loff[i], g_Vtb + b + loff[i]);
        }
        CP_COMMIT();
        CP_WAIT0();
    }
    __syncthreads();

#pragma unroll 1
    for (int ch = 0; ch < 16; ch++) {
        const int cb = (ch & 1) * 8192;
        const bool more = (ch + 1 < 16);
        if (more) {
            const int nc = ch + 1, t = nc >> 2;
            const int sw = (t == 0) ? s0 : (t == 1) ? s1 : (t == 2) ? s2_ : s3;
            const size_t b = ((size_t)(sw * 8 + h)) * 32768 + (size_t)(nc & 3) * 8192;
            const int nb = cb ^ 8192;
#pragma unroll
            for (int i = 0; i < 2; i++) {
                CP_ASYNC16(sK + nb + loff[i], g_Ktb + b + loff[i]);
                CP_ASYNC16(sV + nb + loff[i], g_Vtb + b + loff[i]);
            }
            CP_COMMIT();
        }

#pragma unroll
        for (int np = 0; np < 4; np++) {
            float s2[2][2][4];
#pragma unroll
            for (int mt = 0; mt < 2; mt++)
#pragma unroll
                for (int n8 = 0; n8 < 2; n8++)
#pragma unroll
                    for (int j = 0; j < 4; j++) s2[mt][n8][j] = 0.f;
#pragma unroll
            for (int chk = 0; chk < 2; chk++) {
                const int row = np * 16 + (lane & 7) + ((lane >> 4) << 3);
                const int c = chk * 2 + ((lane >> 3) & 1);
                uint32_t b0, b1, b2, b3;
                ldsm_x4(b0, b1, b2, b3, sK + cb + row * 128 + ((c ^ (row & 7)) * 16));
                uint32_t f0[2] = {b0, b1}, f1[2] = {b2, b3};
#pragma unroll
                for (int mt = 0; mt < 2; mt++) {
                    mma16816h(s2[mt][0], qh[mt][chk], f0);
                    mma16816h(s2[mt][1], qh[mt][chk], f1);
                }
            }
            uint32_t aP[2][4];
#pragma unroll
            for (int mt = 0; mt < 2; mt++) {
                aP[mt][0] = exp2_h2(s2[mt][0][1], s2[mt][0][0]);
                aP[mt][1] = exp2_h2(s2[mt][0][3], s2[mt][0][2]);
                aP[mt][2] = exp2_h2(s2[mt][1][1], s2[mt][1][0]);
                aP[mt][3] = exp2_h2(s2[mt][1][3], s2[mt][1][2]);
            }
#pragma unroll
            for (int mt = 0; mt < 2; mt++)
                mma16816h(lacc[mt], aP[mt], bones);
            uint32_t bV[4][2];
#pragma unroll
            for (int cp = 0; cp < 2; cp++) {
                const int row = np * 16 + (lane & 15);
                const int c = cp * 2 + (lane >> 4);
                uint32_t b0, b1, b2, b3;
                ldsm_x4_t(b0, b1, b2, b3, sV + cb + row * 128 + ((c ^ (row & 7)) * 16));
                bV[cp * 2][0] = b0; bV[cp * 2][1] = b1;
                bV[cp * 2 + 1][0] = b2; bV[cp * 2 + 1][1] = b3;
            }
#pragma unroll
            for (int mt = 0; mt < 2; mt++)
#pragma unroll
                for (int ct = 0; ct < 4; ct++)
                    mma16816h(outA[mt][ct], aP[mt], bV[ct]);
        }

        if (more) CP_WAIT0();
        __syncthreads();
    }

    const int wy = p / 7, wx = p % 7;
#pragma unroll
    for (int mt = 0; mt < 2; mt++)
#pragma unroll
        for (int hf = 0; hf < 2; hf++) {
            const float inv = 1.f / lacc[mt][hf * 2];
            const int q = qz * 128 + wid * 32 + mt * 16 + r + hf * 8;
            const int gy = wy * 16 + (q >> 4), gx = wx * 16 + (q & 15);
            float* o = g_y + ((size_t)(gy * IMG + gx)) * 256 + h * 32;
#pragma unroll
            for (int ct = 0; ct < 4; ct++) {
                float2 v = {outA[mt][ct][hf * 2] * inv, outA[mt][ct][hf * 2 + 1] * inv};
                *(float2*)(o + ct * 8 + c2) = v;
            }
        }
}

// ---------------------------------------------------------------------------
// LePE + add attn; emit fp16 hi rows for out-gemm
// ---------------------------------------------------------------------------
__global__ __launch_bounds__(256) void lepe_k(const float* __restrict__ lw,
                                              const float* __restrict__ lb) {
    const int pix = blockIdx.x;
    const int c   = threadIdx.x;
    const int y = pix / IMG, x = pix % IMG;
    float sum = lb[c];
#pragma unroll
    for (int dy = -1; dy <= 1; dy++) {
        const int yy = y + dy;
        if (yy < 0 || yy >= IMG) continue;
#pragma unroll
        for (int dx = -1; dx <= 1; dx++) {
            const int xx = x + dx;
            if (xx < 0 || xx >= IMG) continue;
            const float v = g_vimg[((size_t)(yy * IMG + xx)) * 256 + c];
            sum += v * lw[((dy + 1) * 3 + (dx + 1)) * 256 + c];
        }
    }
    const float tot = g_y[(size_t)pix * 256 + c] + sum;
    g_Yp[(size_t)pix * 512 + c] = __float2half_rn(tot);
}

// ---------------------------------------------------------------------------
extern "C" void kernel_launch(void* const* d_in, const int* in_sizes, int n_in,
                              void* d_out, int out_size) {
    const float* x      = (const float*)d_in[0];
    const float* w_qkv  = (const float*)d_in[1];
    const float* b_qkv  = (const float*)d_in[2];
    const float* w_o    = (const float*)d_in[3];
    const float* b_o    = (const float*)d_in[4];
    const float* lepe_w = (const float*)d_in[5];
    const float* lepe_b = (const float*)d_in[6];
    float* out = (float*)d_out;
    (void)in_sizes; (void)n_in; (void)out_size;

    prep_w<<<NQKV, 256>>>(w_qkv, w_o);                                       // 1
    nop_k<<<1, 32>>>();                                                      // 2
    nop_k<<<1, 32>>>();                                                      // 3
    gemm_mma<0><<<dim3(NQKV / 128, MROWS / 128), 256>>>(x, b_qkv, nullptr);  // 4 <- ncu
    route_k<<<P2, 256>>>();                                                  // 5
    attn_mma<<<dim3(P2, 8, 2), 128>>>();                                     // 6
    lepe_k<<<IMG * IMG, 256>>>(lepe_w, lepe_b);                              // 7
    gemm_mma<1><<<dim3(KDIM / 128, MROWS / 128), 256>>>(nullptr, b_o, out);  // 8
}

// round 17
// speedup vs baseline: 1.1083x; 1.1083x over previous
#include <cuda_runtime.h>
#include <cuda_bf16.h>
#include <cuda_fp16.h>
#include <cstdint>

// ---------------------------------------------------------------------------
// BiLevelRoutingAttention, B=1, H=W=112, DIM=QK=256, HEADS=8, NWIN=7, TOPK=4
// gemm0/gemm1: single-term fp16, A/B register-prefetched, 2 CTAs/SM.
// KV pack staged through smem (block-local head slots). Attention v8.
// ---------------------------------------------------------------------------

#define P2     49
#define W2     256
#define MROWS  12544
#define NQKV   768
#define KDIM   256
#define IMG    112
#define QSCALE 0.09016844f   // 256^-0.5 * log2(e)

__device__ float g_qkv [MROWS * 512];              // q (stride 512)
__device__ float g_vimg[MROWS * 256];              // v, image layout
__device__ float g_part2[98][512];                 // per half-window column sums
__device__ int   g_top [P2 * 4];
__device__ float g_y   [MROWS * 256];              // attn out, image layout
__device__ __half g_Ap[MROWS * 256];               // x gathered, fp16 compact
__device__ __half g_Yp[MROWS * 256];               // attn+lepe, fp16 compact
__device__ __half g_Bq[NQKV * 256];                // w_qkv^T fp16 compact
__device__ __half g_Bo[KDIM * 256];                // w_o^T fp16 compact
// Packed K/V tiles (fp16): per (win,h): 256 rows x 128B; only hi half used.
__device__ unsigned char g_Ktb[P2 * 8 * 32768];
__device__ unsigned char g_Vtb[P2 * 8 * 32768];

__device__ __forceinline__ uint32_t smem_u32(const void* p) {
    uint32_t a;
    asm("{ .reg .u64 t; cvta.to.shared.u64 t, %1; cvt.u32.u64 %0, t; }" : "=r"(a) : "l"(p));
    return a;
}
__device__ __forceinline__ uint32_t pack_h2(__half lo, __half hi) {
    return ((uint32_t)__half_as_ushort(hi) << 16) | __half_as_ushort(lo);
}
__device__ __forceinline__ uint32_t exp2_h2(float hi, float lo) {
    uint32_t d;
    asm("cvt.rn.f16x2.f32 %0, %1, %2;" : "=r"(d) : "f"(hi), "f"(lo));
    asm("sub.f16x2 %0, %0, %1;" : "+r"(d) : "r"(0x46004600u));   // 6.0 | 6.0
    asm("ex2.approx.f16x2 %0, %0;" : "+r"(d));
    return d;
}
__device__ __forceinline__ void ldsm_x4(uint32_t& r0, uint32_t& r1, uint32_t& r2, uint32_t& r3, uint32_t a) {
    asm volatile("ldmatrix.sync.aligned.m8n8.x4.shared.b16 {%0,%1,%2,%3}, [%4];"
                 : "=r"(r0), "=r"(r1), "=r"(r2), "=r"(r3) : "r"(a));
}
__device__ __forceinline__ void ldsm_x4_t(uint32_t& r0, uint32_t& r1, uint32_t& r2, uint32_t& r3, uint32_t a) {
    asm volatile("ldmatrix.sync.aligned.m8n8.x4.trans.shared.b16 {%0,%1,%2,%3}, [%4];"
                 : "=r"(r0), "=r"(r1), "=r"(r2), "=r"(r3) : "r"(a));
}
__device__ __forceinline__ void mma16816h(float* c, const uint32_t* a, const uint32_t* b) {
    asm volatile(
        "mma.sync.aligned.m16n8k16.row.col.f32.f16.f16.f32 "
        "{%0,%1,%2,%3}, {%4,%5,%6,%7}, {%8,%9}, {%0,%1,%2,%3};"
        : "+f"(c[0]), "+f"(c[1]), "+f"(c[2]), "+f"(c[3])
        : "r"(a[0]), "r"(a[1]), "r"(a[2]), "r"(a[3]), "r"(b[0]), "r"(b[1]));
}
#define CP_ASYNC16(sa, gp) asm volatile("cp.async.cg.shared.global [%0], [%1], 16;" :: "r"(sa), "l"(gp) : "memory")
#define CP_COMMIT()        asm volatile("cp.async.commit_group;" ::: "memory")
#define CP_WAIT0()         asm volatile("cp.async.wait_group 0;" ::: "memory")

// ---------------------------------------------------------------------------
// Prep kernels
// ---------------------------------------------------------------------------
__global__ __launch_bounds__(256) void prep_w(const float* __restrict__ wq,
                                              const float* __restrict__ wo) {
    const int t = blockIdx.x * 256 + threadIdx.x;
    const int n = t >> 8, k = t & 255;
    g_Bq[n * 256 + k] = __float2half_rn(wq[k * NQKV + n]);
    if (t < KDIM * KDIM)
        g_Bo[n * 256 + k] = __float2half_rn(wo[k * KDIM + n]);
}
__global__ __launch_bounds__(256) void prep_a(const float* __restrict__ x) {
    const int m = blockIdx.x, c = threadIdx.x;
    const int p = m >> 8, pix = m & 255;
    const int gy = (p / 7) * 16 + (pix >> 4);
    const int gx = (p % 7) * 16 + (pix & 15);
    g_Ap[m * 256 + c] = __float2half_rn(x[(gy * IMG + gx) * KDIM + c]);
}
__global__ void nop_k() {}

// ---------------------------------------------------------------------------
// Dense GEMM fp16 single-term, 4 k-tiles, A/B register-prefetched, 2 CTAs/SM.
// MODE 0: epilogue fuses KV pack (smem-staged) + v scatter + column sums.
// ---------------------------------------------------------------------------
template <int MODE>
__global__ __launch_bounds__(256, 2) void gemm_mma(const float* __restrict__ bias,
                                                   float* __restrict__ Cout) {
    __shared__ __align__(128) unsigned char SM[32768 + 2048];
    float (*sWsum)[64] = (float(*)[64])(SM + 32768);

    const __half* A = (MODE == 0) ? g_Ap : g_Yp;
    const __half* B = (MODE == 0) ? g_Bq : g_Bo;

    const int tid  = threadIdx.x;
    const int wid  = tid >> 5;
    const int lane = tid & 31;
    const int m0   = blockIdx.y * 128;
    const int n0   = blockIdx.x * 128;
    const int mw   = (wid >> 1) * 32;
    const int nw   = (wid & 1) * 64;

    const uint32_t sA = smem_u32(SM), sB = sA + 16384;

    int grow[4], gchk[4], soff[4];
#pragma unroll
    for (int i = 0; i < 4; i++) {
        const int idx = tid + 256 * i;
        grow[i] = idx >> 3;
        gchk[i] = idx & 7;
        soff[i] = grow[i] * 128 + ((gchk[i] ^ (grow[i] & 7)) * 16);
    }

    uint4 pa[4], pb[4];
#pragma unroll
    for (int i = 0; i < 4; i++) {
        pa[i] = *(const uint4*)(A + (size_t)(m0 + grow[i]) * 256 + gchk[i] * 8);
        pb[i] = *(const uint4*)(B + (size_t)(n0 + grow[i]) * 256 + gchk[i] * 8);
    }

    float acc[2][8][4];
#pragma unroll
    for (int mt = 0; mt < 2; mt++)
#pragma unroll
        for (int nt = 0; nt < 8; nt++)
#pragma unroll
            for (int j = 0; j < 4; j++) acc[mt][nt][j] = 0.f;

    for (int kt = 0; kt < 4; kt++) {
#pragma unroll
        for (int i = 0; i < 4; i++) {
            *(uint4*)(SM + soff[i])         = pa[i];
            *(uint4*)(SM + 16384 + soff[i]) = pb[i];
        }
        __syncthreads();
        if (kt + 1 < 4) {
            const int ko = (kt + 1) * 64;
#pragma unroll
            for (int i = 0; i < 4; i++) {
                pa[i] = *(const uint4*)(A + (size_t)(m0 + grow[i]) * 256 + ko + gchk[i] * 8);
                pb[i] = *(const uint4*)(B + (size_t)(n0 + grow[i]) * 256 + ko + gchk[i] * 8);
            }
        }
#pragma unroll
        for (int ks = 0; ks < 4; ks++) {
            uint32_t aF[2][4];
#pragma unroll
            for (int mt = 0; mt < 2; mt++) {
                const int row = mw + mt * 16 + (lane & 15);
                const int chk = ks * 2 + (lane >> 4);
                ldsm_x4(aF[mt][0], aF[mt][1], aF[mt][2], aF[mt][3],
                        sA + row * 128 + ((chk ^ (row & 7)) * 16));
            }
            uint32_t bF[8][2];
#pragma unroll
            for (int np = 0; np < 4; np++) {
                const int row = nw + np * 16 + (lane & 7) + ((lane >> 4) << 3);
                const int chk = ks * 2 + ((lane >> 3) & 1);
                uint32_t r0, r1, r2, r3;
                ldsm_x4(r0, r1, r2, r3, sB + row * 128 + ((chk ^ (row & 7)) * 16));
                bF[np * 2][0] = r0; bF[np * 2][1] = r1;
                bF[np * 2 + 1][0] = r2; bF[np * 2 + 1][1] = r3;
            }
#pragma unroll
            for (int mt = 0; mt < 2; mt++)
#pragma unroll
                for (int nt = 0; nt < 8; nt++)
                    mma16816h(acc[mt][nt], aF[mt], bF[nt]);
        }
        __syncthreads();
    }

    const int r0 = lane >> 2, c0 = (lane & 3) * 2;
    const int kind = (MODE == 0) ? ((n0 >= 512) ? 2 : ((n0 >= 256) ? 1 : 0)) : 0;

    float cs[8][2];
#pragma unroll
    for (int nt = 0; nt < 8; nt++) { cs[nt][0] = 0.f; cs[nt][1] = 0.f; }

#pragma unroll
    for (int mt = 0; mt < 2; mt++) {
#pragma unroll
        for (int nt = 0; nt < 8; nt++) {
            const int col = n0 + nw + nt * 8 + c0;
            const float bx = bias[col], by = bias[col + 1];
            const int rowa = m0 + mw + mt * 16 + r0;
            const float vx[2] = {acc[mt][nt][0] + bx, acc[mt][nt][2] + bx};
            const float vy[2] = {acc[mt][nt][1] + by, acc[mt][nt][3] + by};
            if (MODE == 1) {
                *(float2*)(Cout + (size_t)rowa * KDIM + col)       = make_float2(vx[0], vy[0]);
                *(float2*)(Cout + (size_t)(rowa + 8) * KDIM + col) = make_float2(vx[1], vy[1]);
            } else {
                cs[nt][0] += vx[0] + vx[1];
                cs[nt][1] += vy[0] + vy[1];
#pragma unroll
                for (int rr = 0; rr < 2; rr++) {
                    const int row = rowa + rr * 8;
                    if (kind == 0)
                        *(float2*)(g_qkv + (size_t)row * 512 + col) = make_float2(vx[rr], vy[rr]);
                    if (kind >= 1) {
                        const int hl = (col - n0) >> 5;          // block-local head 0..3
                        const int w  = ((col - n0) & 31) >> 1;
                        const int jl = mw + mt * 16 + r0 + rr * 8;
                        *(uint32_t*)(SM + hl * 8192 + jl * 64 + (w >> 2) * 16 + (w & 3) * 4)
                            = pack_h2(__float2half_rn(vx[rr]), __float2half_rn(vy[rr]));
                    }
                    if (kind == 2) {
                        const int p = row >> 8, pix = row & 255;
                        const int gy = (p / 7) * 16 + (pix >> 4);
                        const int gx = (p % 7) * 16 + (pix & 15);
                        *(float2*)(g_vimg + ((size_t)(gy * IMG + gx)) * 256 + (col - 512))
                            = make_float2(vx[rr], vy[rr]);
                    }
                }
            }
        }
    }

    if (MODE == 0 && kind >= 1) {
        __syncthreads();
        const int pwin  = m0 >> 8;
        const int jbase = m0 & 255;
        const int hbase = (n0 - ((kind == 1) ? 256 : 512)) >> 5;   // 0 or 4
        unsigned char* tb0 = ((kind == 1) ? g_Ktb : g_Vtb)
                           + ((size_t)pwin * 8 + hbase) * 32768;
#pragma unroll
        for (int i = 0; i < 8; i++) {
            const int idx = tid + i * 256;
            const int hh = idx >> 9;
            const int j  = (idx >> 2) & 127;
            const int sl = idx & 3;
            const int jj = jbase + j;
            *(uint4*)(tb0 + (size_t)hh * 32768 + jj * 128 + ((sl ^ (jj & 7)) * 16))
                = *(const uint4*)(SM + hh * 8192 + j * 64 + sl * 16);
        }
    }

    if (MODE == 0 && kind < 2) {
#pragma unroll
        for (int nt = 0; nt < 8; nt++) {
            float a = cs[nt][0], b = cs[nt][1];
#pragma unroll
            for (int o = 4; o < 32; o <<= 1) {
                a += __shfl_xor_sync(0xffffffffu, a, o);
                b += __shfl_xor_sync(0xffffffffu, b, o);
            }
            if (lane < 4) {
                sWsum[wid][nt * 8 + c0]     = a;
                sWsum[wid][nt * 8 + c0 + 1] = b;
            }
        }
        __syncthreads();
        if (tid < 128) {
            const int nwsel = tid >> 6, col = tid & 63;
            const float s = sWsum[nwsel][col] + sWsum[2 + nwsel][col]
                          + sWsum[4 + nwsel][col] + sWsum[6 + nwsel][col];
            g_part2[m0 >> 7][n0 + nwsel * 64 + col] = s;
        }
    }
}

// ---------------------------------------------------------------------------
// Routing: block p: q-row sum, logits vs all k-row sums, top-4.
// ---------------------------------------------------------------------------
__global__ __launch_bounds__(256) void route_k() {
    __shared__ float sq[256];
    __shared__ float slog[64];
    const int p = blockIdx.x, tid = threadIdx.x, wrp = tid >> 5, lane = tid & 31;

    sq[tid] = g_part2[2 * p][tid] + g_part2[2 * p + 1][tid];
    __syncthreads();

    const float q0 = sq[lane * 8 + 0], q1 = sq[lane * 8 + 1];
    const float q2 = sq[lane * 8 + 2], q3 = sq[lane * 8 + 3];
    const float q4 = sq[lane * 8 + 4], q5 = sq[lane * 8 + 5];
    const float q6 = sq[lane * 8 + 6], q7 = sq[lane * 8 + 7];
    for (int j = wrp; j < P2; j += 8) {
        const float4 a0 = *(const float4*)&g_part2[2 * j][256 + lane * 8];
        const float4 a1 = *(const float4*)&g_part2[2 * j][256 + lane * 8 + 4];
        const float4 b0 = *(const float4*)&g_part2[2 * j + 1][256 + lane * 8];
        const float4 b1 = *(const float4*)&g_part2[2 * j + 1][256 + lane * 8 + 4];
        float d = q0 * (a0.x + b0.x) + q1 * (a0.y + b0.y)
                + q2 * (a0.z + b0.z) + q3 * (a0.w + b0.w)
                + q4 * (a1.x + b1.x) + q5 * (a1.y + b1.y)
                + q6 * (a1.z + b1.z) + q7 * (a1.w + b1.w);
#pragma unroll
        for (int o = 16; o > 0; o >>= 1) d += __shfl_xor_sync(0xffffffffu, d, o);
        if (lane == 0) slog[j] = d;
    }
    __syncthreads();

    if (tid == 0) {
        float bv0 = -1e30f, bv1 = -1e30f, bv2 = -1e30f, bv3 = -1e30f;
        int   bi0 = 0, bi1 = 0, bi2 = 0, bi3 = 0;
        for (int j = 0; j < P2; j++) {
            const float s = slog[j];
            if (s > bv3) {
                if (s > bv0)      { bv3=bv2;bi3=bi2; bv2=bv1;bi2=bi1; bv1=bv0;bi1=bi0; bv0=s;bi0=j; }
                else if (s > bv1) { bv3=bv2;bi3=bi2; bv2=bv1;bi2=bi1; bv1=s;bi1=j; }
                else if (s > bv2) { bv3=bv2;bi3=bi2; bv2=s;bi2=j; }
                else              { bv3=s;bi3=j; }
            }
        }
        g_top[p * 4 + 0] = bi0; g_top[p * 4 + 1] = bi1;
        g_top[p * 4 + 2] = bi2; g_top[p * 4 + 3] = bi3;
    }
}

// ---------------------------------------------------------------------------
// Attention v8 (validated R16): grid (49, 8, 2); 128 threads; per-key-group
// pipeline; cp.async K/V fills.
// ---------------------------------------------------------------------------
__global__ __launch_bounds__(128) void attn_mma() {
    __shared__ __align__(128) unsigned char Kt[16384];
    __shared__ __align__(128) unsigned char Vt[16384];
    __shared__ int sidx[4];
    const int p = blockIdx.x, h = blockIdx.y, qz = blockIdx.z;
    const int tid = threadIdx.x, wid = tid >> 5, lane = tid & 31;
    if (tid < 4) sidx[tid] = g_top[p * 4 + tid];

    const uint32_t sK = smem_u32(Kt), sV = smem_u32(Vt);
    const int r  = lane >> 2;
    const int c2 = (lane & 3) * 2;

    int loff[2];
#pragma unroll
    for (int i = 0; i < 2; i++) {
        const int t = tid + i * 128;
        const int lrow = t >> 2, lc = t & 3;
        loff[i] = lrow * 128 + ((lc ^ (lrow & 7)) * 16);
    }

    uint32_t qh[2][2][4];
    {
        const float* qb = g_qkv + ((size_t)p * W2 + qz * 128 + wid * 32) * 512 + h * 32;
#pragma unroll
        for (int mt = 0; mt < 2; mt++)
#pragma unroll
            for (int ks = 0; ks < 2; ks++)
#pragma unroll
                for (int idx = 0; idx < 4; idx++) {
                    const int row = mt * 16 + r + (idx & 1) * 8;
                    const int col = ks * 16 + (idx >> 1) * 8 + c2;
                    const float2 v = *(const float2*)(qb + (size_t)row * 512 + col);
                    qh[mt][ks][idx] = pack_h2(__float2half_rn(v.x * QSCALE),
                                              __float2half_rn(v.y * QSCALE));
                }
    }
    __syncthreads();
    const int s0 = sidx[0], s1 = sidx[1], s2_ = sidx[2], s3 = sidx[3];

    float lacc[2][4];
    float outA[2][4][4];
#pragma unroll
    for (int mt = 0; mt < 2; mt++) {
#pragma unroll
        for (int j = 0; j < 4; j++) lacc[mt][j] = 0.f;
#pragma unroll
        for (int ct = 0; ct < 4; ct++)
#pragma unroll
            for (int j = 0; j < 4; j++) outA[mt][ct][j] = 0.f;
    }
    const uint32_t ONE2 = 0x3C003C00u;
    const uint32_t bones[2] = {ONE2, ONE2};

    {
        const size_t b = ((size_t)(s0 * 8 + h)) * 32768;
#pragma unroll
        for (int i = 0; i < 2; i++) {
            CP_ASYNC16(sK + loff[i], g_Ktb + b + loff[i]);
            CP_ASYNC16(sV + loff[i], g_Vtb + b + loff[i]);
        }
        CP_COMMIT();
        CP_WAIT0();
    }
    __syncthreads();

#pragma unroll 1
    for (int ch = 0; ch < 16; ch++) {
        const int cb = (ch & 1) * 8192;
        const bool more = (ch + 1 < 16);
        if (more) {
            const int nc = ch + 1, t = nc >> 2;
            const int sw = (t == 0) ? s0 : (t == 1) ? s1 : (t == 2) ? s2_ : s3;
            const size_t b = ((size_t)(sw * 8 + h)) * 32768 + (size_t)(nc & 3) * 8192;
            const int nb = cb ^ 8192;
#pragma unroll
            for (int i = 0; i < 2; i++) {
                CP_ASYNC16(sK + nb + loff[i], g_Ktb + b + loff[i]);
                CP_ASYNC16(sV + nb + loff[i], g_Vtb + b + loff[i]);
            }
            CP_COMMIT();
        }

#pragma unroll
        for (int np = 0; np < 4; np++) {
            float s2[2][2][4];
#pragma unroll
            for (int mt = 0; mt < 2; mt++)
#pragma unroll
                for (int n8 = 0; n8 < 2; n8++)
#pragma unroll
                    for (int j = 0; j < 4; j++) s2[mt][n8][j] = 0.f;
#pragma unroll
            for (int chk = 0; chk < 2; chk++) {
                const int row = np * 16 + (lane & 7) + ((lane >> 4) << 3);
                const int c = chk * 2 + ((lane >> 3) & 1);
                uint32_t b0, b1, b2, b3;
                ldsm_x4(b0, b1, b2, b3, sK + cb + row * 128 + ((c ^ (row & 7)) * 16));
                uint32_t f0[2] = {b0, b1}, f1[2] = {b2, b3};
#pragma unroll
                for (int mt = 0; mt < 2; mt++) {
                    mma16816h(s2[mt][0], qh[mt][chk], f0);
                    mma16816h(s2[mt][1], qh[mt][chk], f1);
                }
            }
            uint32_t aP[2][4];
#pragma unroll
            for (int mt = 0; mt < 2; mt++) {
                aP[mt][0] = exp2_h2(s2[mt][0][1], s2[mt][0][0]);
                aP[mt][1] = exp2_h2(s2[mt][0][3], s2[mt][0][2]);
                aP[mt][2] = exp2_h2(s2[mt][1][1], s2[mt][1][0]);
                aP[mt][3] = exp2_h2(s2[mt][1][3], s2[mt][1][2]);
            }
#pragma unroll
            for (int mt = 0; mt < 2; mt++)
                mma16816h(lacc[mt], aP[mt], bones);
            uint32_t bV[4][2];
#pragma unroll
            for (int cp = 0; cp < 2; cp++) {
                const int row = np * 16 + (lane & 15);
                const int c = cp * 2 + (lane >> 4);
                uint32_t b0, b1, b2, b3;
                ldsm_x4_t(b0, b1, b2, b3, sV + cb + row * 128 + ((c ^ (row & 7)) * 16));
                bV[cp * 2][0] = b0; bV[cp * 2][1] = b1;
                bV[cp * 2 + 1][0] = b2; bV[cp * 2 + 1][1] = b3;
            }
#pragma unroll
            for (int mt = 0; mt < 2; mt++)
#pragma unroll
                for (int ct = 0; ct < 4; ct++)
                    mma16816h(outA[mt][ct], aP[mt], bV[ct]);
        }

        if (more) CP_WAIT0();
        __syncthreads();
    }

    const int wy = p / 7, wx = p % 7;
#pragma unroll
    for (int mt = 0; mt < 2; mt++)
#pragma unroll
        for (int hf = 0; hf < 2; hf++) {
            const float inv = 1.f / lacc[mt][hf * 2];
            const int q = qz * 128 + wid * 32 + mt * 16 + r + hf * 8;
            const int gy = wy * 16 + (q >> 4), gx = wx * 16 + (q & 15);
            float* o = g_y + ((size_t)(gy * IMG + gx)) * 256 + h * 32;
#pragma unroll
            for (int ct = 0; ct < 4; ct++) {
                float2 v = {outA[mt][ct][hf * 2] * inv, outA[mt][ct][hf * 2 + 1] * inv};
                *(float2*)(o + ct * 8 + c2) = v;
            }
        }
}

// ---------------------------------------------------------------------------
// LePE + add attn; emit fp16 compact rows for out-gemm
// ---------------------------------------------------------------------------
__global__ __launch_bounds__(256) void lepe_k(const float* __restrict__ lw,
                                              const float* __restrict__ lb) {
    const int pix = blockIdx.x;
    const int c   = threadIdx.x;
    const int y = pix / IMG, x = pix % IMG;
    float sum = lb[c];
#pragma unroll
    for (int dy = -1; dy <= 1; dy++) {
        const int yy = y + dy;
        if (yy < 0 || yy >= IMG) continue;
#pragma unroll
        for (int dx = -1; dx <= 1; dx++) {
            const int xx = x + dx;
            if (xx < 0 || xx >= IMG) continue;
            const float v = g_vimg[((size_t)(yy * IMG + xx)) * 256 + c];
            sum += v * lw[((dy + 1) * 3 + (dx + 1)) * 256 + c];
        }
    }
    const float tot = g_y[(size_t)pix * 256 + c] + sum;
    g_Yp[(size_t)pix * 256 + c] = __float2half_rn(tot);
}

// ---------------------------------------------------------------------------
extern "C" void kernel_launch(void* const* d_in, const int* in_sizes, int n_in,
                              void* d_out, int out_size) {
    const float* x      = (const float*)d_in[0];
    const float* w_qkv  = (const float*)d_in[1];
    const float* b_qkv  = (const float*)d_in[2];
    const float* w_o    = (const float*)d_in[3];
    const float* b_o    = (const float*)d_in[4];
    const float* lepe_w = (const float*)d_in[5];
    const float* lepe_b = (const float*)d_in[6];
    float* out = (float*)d_out;
    (void)in_sizes; (void)n_in; (void)out_size;

    prep_w<<<NQKV, 256>>>(w_qkv, w_o);                                    // 1
    prep_a<<<MROWS, 256>>>(x);                                            // 2
    nop_k<<<1, 32>>>();                                                   // 3
    gemm_mma<0><<<dim3(NQKV / 128, MROWS / 128), 256>>>(b_qkv, nullptr);  // 4 <- ncu
    route_k<<<P2, 256>>>();                                               // 5
    attn_mma<<<dim3(P2, 8, 2), 128>>>();                                  // 6
    lepe_k<<<IMG * IMG, 256>>>(lepe_w, lepe_b);                           // 7
    gemm_mma<1><<<dim3(KDIM / 128, MROWS / 128), 256>>>(b_o, out);        // 8
}